// round 12
// baseline (speedup 1.0000x reference)
#include <cuda_runtime.h>
#include <cuda_bf16.h>
#include <cuda_fp16.h>
#include <math.h>

#define HDIM 64
#define KDIM 256
#define HW   65536
#define NPTS 262144
#define RATE_F 0.999f
#define EPS_F  1e-6f
#define SXPAD 68           // padded x-tile row (floats); 272B, 16B-aligned

typedef unsigned long long u64;

// Persistent device scratch (allocation-free rule).
__device__ __align__(16) float g_m  [KDIM * HDIM];   // codebook [k][c]
__device__ __align__(16) float g_mn [KDIM * HDIM];   // normalized [k][c] (for out)
__device__ __align__(16) float g_mnT[HDIM * KDIM];   // normalized transposed [c][k] (assign)
__device__ __align__(16) float g_sum[KDIM * HDIM];
__device__ float g_cnt[KDIM];
__device__ float g_nrm[KDIM];

// ---- packed f32x2 helpers (FFMA2: 2 MACs / issue slot on sm_103a) ----
__device__ __forceinline__ u64 pack2(float lo, float hi) {
    u64 r; asm("mov.b64 %0, {%1, %2};" : "=l"(r) : "f"(lo), "f"(hi)); return r;
}
__device__ __forceinline__ void unpack2(u64 v, float& lo, float& hi) {
    asm("mov.b64 {%0, %1}, %2;" : "=f"(lo), "=f"(hi) : "l"(v));
}
__device__ __forceinline__ void fma2(u64& d, u64 a, u64 b) {
    asm("fma.rn.f32x2 %0, %1, %2, %0;" : "+l"(d) : "l"(a), "l"(b));
}
__device__ __forceinline__ u64 add2(u64 a, u64 b) {
    u64 r; asm("add.rn.f32x2 %0, %1, %2;" : "=l"(r) : "l"(a), "l"(b)); return r;
}
__device__ __forceinline__ float ex2f(float x) {
    float r; asm("ex2.approx.f32 %0, %1;" : "=f"(r) : "f"(x)); return r;
}

// ---------------------------------------------------------------------------
// prep: m = units; mn = normalize(m); mnT transposed copy; nrm; zero sums.
// ---------------------------------------------------------------------------
__global__ void prep_kernel(const float* __restrict__ units) {
    int warp = threadIdx.x >> 5, lane = threadIdx.x & 31;
    int k = blockIdx.x * 8 + warp;
    if (k >= KDIM) return;
    float v0 = units[k * HDIM + lane];
    float v1 = units[k * HDIM + 32 + lane];
    g_m[k * HDIM + lane]      = v0;
    g_m[k * HDIM + 32 + lane] = v1;
    float ssq = v0 * v0 + v1 * v1;
    #pragma unroll
    for (int o = 16; o; o >>= 1) ssq += __shfl_xor_sync(0xFFFFFFFFu, ssq, o);
    float nrm = sqrtf(ssq);
    float inv = 1.0f / fmaxf(nrm, 1e-12f);
    g_mn[k * HDIM + lane]      = v0 * inv;
    g_mn[k * HDIM + 32 + lane] = v1 * inv;
    g_mnT[lane * KDIM + k]        = v0 * inv;
    g_mnT[(32 + lane) * KDIM + k] = v1 * inv;
    g_sum[k * HDIM + lane]      = 0.0f;
    g_sum[k * HDIM + 32 + lane] = 0.0f;
    if (lane == 0) { g_cnt[k] = 0.0f; g_nrm[k] = nrm; }
}

// ---------------------------------------------------------------------------
// assign (R11 form): CTA = 64 pts x 256 k, double-buffered operands.
// ---------------------------------------------------------------------------
__global__ void __launch_bounds__(256, 2) assign_kernel(const float* __restrict__ x) {
    extern __shared__ float smem[];
    float* smnT = smem;                    // [64 c][256 k] = 64 KB
    float* sx   = smem + HDIM * KDIM;      // [64 c][SXPAD] = 17 KB

    {
        const ulonglong2* gm = (const ulonglong2*)g_mnT;
        ulonglong2* sm2 = (ulonglong2*)smnT;
        #pragma unroll 4
        for (int i = threadIdx.x; i < HDIM * KDIM / 4; i += 256) sm2[i] = gm[i];
    }
    int hw0 = blockIdx.x * 64;
    int b   = hw0 >> 16;
    const float* xg = x + (size_t)b * HDIM * HW + (hw0 & (HW - 1));
    #pragma unroll 4
    for (int i = threadIdx.x; i < HDIM * 64; i += 256) {
        int c = i >> 6, pt = i & 63;
        sx[c * SXPAD + pt] = xg[(size_t)c * HW + pt];
    }
    __syncthreads();

    int w = threadIdx.x >> 5, lane = threadIdx.x & 31;
    int ptBase = 8 * w;

    u64 acc[4][8];
    #pragma unroll
    for (int pp = 0; pp < 4; pp++)
        #pragma unroll
        for (int j = 0; j < 8; j++) acc[pp][j] = 0ull;

    float mnf[8];
    ulonglong2 xq0, xq1;
    {
        const ulonglong2* xr = (const ulonglong2*)(sx + ptBase);
        xq0 = xr[0]; xq1 = xr[1];
        const float* mrow = smnT + lane;
        #pragma unroll
        for (int j = 0; j < 8; j++) mnf[j] = mrow[32 * j];
    }

    #pragma unroll 2
    for (int c = 0; c < HDIM; c++) {
        int cn = (c + 1) & (HDIM - 1);
        const ulonglong2* xrn = (const ulonglong2*)(sx + cn * SXPAD + ptBase);
        ulonglong2 xn0 = xrn[0], xn1 = xrn[1];
        const float* mrown = smnT + cn * KDIM + lane;
        float mnfn[8];
        #pragma unroll
        for (int j = 0; j < 8; j++) mnfn[j] = mrown[32 * j];

        u64 xp0 = xq0.x, xp1 = xq0.y, xp2 = xq1.x, xp3 = xq1.y;
        u64 mnd[8];
        #pragma unroll
        for (int j = 0; j < 8; j++) mnd[j] = pack2(mnf[j], mnf[j]);
        #pragma unroll
        for (int j = 0; j < 8; j++) {
            fma2(acc[0][j], xp0, mnd[j]);
            fma2(acc[1][j], xp1, mnd[j]);
            fma2(acc[2][j], xp2, mnd[j]);
            fma2(acc[3][j], xp3, mnd[j]);
        }
        xq0 = xn0; xq1 = xn1;
        #pragma unroll
        for (int j = 0; j < 8; j++) mnf[j] = mnfn[j];
    }

    #pragma unroll
    for (int pl = 0; pl < 8; pl++) {
        const int pp = pl >> 1, hi = pl & 1;
        float best = -1e30f; int bj = 0;
        #pragma unroll
        for (int j = 0; j < 8; j++) {
            float lo_, hi_;
            unpack2(acc[pp][j], lo_, hi_);
            float d = hi ? hi_ : lo_;
            if (d > best) { best = d; bj = j; }
        }
        int bk = lane + 32 * bj;
        #pragma unroll
        for (int o = 16; o; o >>= 1) {
            float ov = __shfl_xor_sync(0xFFFFFFFFu, best, o);
            int   ok = __shfl_xor_sync(0xFFFFFFFFu, bk,   o);
            if (ov > best || (ov == best && ok < bk)) { best = ov; bk = ok; }
        }
        int pt = ptBase + pl;
        float v0 = sx[lane * SXPAD + pt];
        float v1 = sx[(32 + lane) * SXPAD + pt];
        atomicAdd(g_sum + bk * HDIM + lane,      v0);
        atomicAdd(g_sum + bk * HDIM + 32 + lane, v1);
        if (lane == 0) atomicAdd(g_cnt + bk, 1.0f);
    }
}

// ---------------------------------------------------------------------------
// update3: closed-form 3-step EMA with frozen assignments.
// ---------------------------------------------------------------------------
__global__ void update3_kernel() {
    int warp = threadIdx.x >> 5, lane = threadIdx.x & 31;
    int k = blockIdx.x * 8 + warp;
    if (k >= KDIM) return;
    const float R3  = RATE_F * RATE_F * RATE_F;
    const float IR3 = 1.0f - R3;
    float sc = IR3 / (g_cnt[k] + EPS_F);
    float m0 = g_m[k * HDIM + lane]      * R3 + g_sum[k * HDIM + lane]      * sc;
    float m1 = g_m[k * HDIM + 32 + lane] * R3 + g_sum[k * HDIM + 32 + lane] * sc;
    g_m[k * HDIM + lane]      = m0;
    g_m[k * HDIM + 32 + lane] = m1;
    float ssq = m0 * m0 + m1 * m1;
    #pragma unroll
    for (int o = 16; o; o >>= 1) ssq += __shfl_xor_sync(0xFFFFFFFFu, ssq, o);
    float nrm = sqrtf(ssq);
    float inv = 1.0f / fmaxf(nrm, 1e-12f);
    g_mn[k * HDIM + lane]      = m0 * inv;
    g_mn[k * HDIM + 32 + lane] = m1 * inv;
    if (lane == 0) g_nrm[k] = nrm;
}

// ---------------------------------------------------------------------------
// out (two-pass, e staged in smem as fp16):
// Pass 1: dot -> ex2 -> den, store w = half(e * nrm_k) in se[k][pt]
//         (own-thread data, [k][pt] layout, conflict-free, NO barrier).
// Pass 2: pure stream: acc[i] += {w,w} * mn_row — fma-pipe bound, no serial
//         chain. smem = mn 64K + e 128K + nrm 1K = 193 KB, 1 CTA x 256 thr/SM.
// ---------------------------------------------------------------------------
__global__ void __launch_bounds__(256, 1) out_kernel(const float* __restrict__ x,
                                                     float* __restrict__ out) {
    extern __shared__ __align__(16) unsigned char sraw[];
    ulonglong2* smq = (ulonglong2*)sraw;                    // mn: 4096 x 16B
    __half* se     = (__half*)(sraw + 65536);               // [256 k][256 pt] fp16
    float*  snrm   = (float*)(sraw + 65536 + 131072);       // 256 floats

    const ulonglong2* gm = (const ulonglong2*)g_mn;
    #pragma unroll 4
    for (int i = threadIdx.x; i < KDIM * HDIM / 4; i += 256) smq[i] = gm[i];
    if (threadIdx.x < KDIM) snrm[threadIdx.x] = g_nrm[threadIdx.x];
    __syncthreads();

    int tid = threadIdx.x;
    int p  = blockIdx.x * 256 + tid;
    int b  = p >> 16;
    const float* xb = x + (size_t)b * HDIM * HW + (p & (HW - 1));

    float xf[HDIM];
    float s0 = 0.f, s1 = 0.f;
    #pragma unroll
    for (int i = 0; i < HDIM; i += 2) {
        float f0 = xb[(size_t)i * HW];
        float f1 = xb[(size_t)(i + 1) * HW];
        xf[i] = f0; xf[i + 1] = f1;
        s0 = fmaf(f0, f0, s0);
        s1 = fmaf(f1, f1, s1);
    }
    float scl = 1.44269504088896f / fmaxf(sqrtf(s0 + s1), 1e-12f);
    u64 xr[HDIM / 2];
    #pragma unroll
    for (int i = 0; i < HDIM / 2; i++)
        xr[i] = pack2(xf[2 * i] * scl, xf[2 * i + 1] * scl);

    // ---- Pass 1: scores -> e -> den; stash w = e*nrm as fp16 ----
    float den = 0.0f;
    for (int k = 0; k < KDIM; k++) {
        const ulonglong2* row = smq + k * 16;
        u64 d0 = 0ull, d1 = 0ull, d2 = 0ull, d3 = 0ull;
        #pragma unroll
        for (int i = 0; i < 8; i++) {
            ulonglong2 qa = row[2 * i];
            ulonglong2 qb = row[2 * i + 1];
            fma2(d0, xr[4 * i + 0], qa.x);
            fma2(d1, xr[4 * i + 1], qa.y);
            fma2(d2, xr[4 * i + 2], qb.x);
            fma2(d3, xr[4 * i + 3], qb.y);
        }
        float e0, e1;
        unpack2(add2(add2(d0, d1), add2(d2, d3)), e0, e1);
        float e = ex2f(e0 + e1);          // exp(score), score in [-1,1]
        den += e;
        se[k * 256 + tid] = __float2half(e * snrm[k]);
    }

    // ---- Pass 2: acc = sum_k w_k * mn_k (pure stream; own-thread smem RAW
    //      needs no barrier) ----
    u64 acc[HDIM / 2];
    #pragma unroll
    for (int i = 0; i < HDIM / 2; i++) acc[i] = 0ull;

    for (int k = 0; k < KDIM; k++) {
        float wv = __half2float(se[k * 256 + tid]);
        u64 w2 = pack2(wv, wv);
        const ulonglong2* row = smq + k * 16;
        #pragma unroll
        for (int i = 0; i < 16; i++) {
            ulonglong2 q = row[i];
            fma2(acc[2 * i],     w2, q.x);
            fma2(acc[2 * i + 1], w2, q.y);
        }
    }

    float iden = 1.0f / den;
    float* ob = out + (size_t)b * HDIM * HW + (p & (HW - 1));
    #pragma unroll
    for (int i = 0; i < HDIM / 2; i++) {
        float f0, f1;
        unpack2(acc[i], f0, f1);
        ob[(size_t)(2 * i) * HW]     = f0 * iden;
        ob[(size_t)(2 * i + 1) * HW] = f1 * iden;
    }
}

// ---------------------------------------------------------------------------
extern "C" void kernel_launch(void* const* d_in, const int* in_sizes, int n_in,
                              void* d_out, int out_size) {
    const float* x;
    const float* units;
    if (in_sizes[0] >= in_sizes[1]) { x = (const float*)d_in[0]; units = (const float*)d_in[1]; }
    else                            { x = (const float*)d_in[1]; units = (const float*)d_in[0]; }
    float* out = (float*)d_out;

    const int assign_bytes = (HDIM * KDIM + HDIM * SXPAD) * (int)sizeof(float); // ~81 KB
    const int out_bytes    = 65536 + 131072 + 1024;                             // 193 KB
    cudaFuncSetAttribute(assign_kernel, cudaFuncAttributeMaxDynamicSharedMemorySize, assign_bytes);
    cudaFuncSetAttribute(out_kernel,    cudaFuncAttributeMaxDynamicSharedMemorySize, out_bytes);

    prep_kernel<<<32, 256>>>(units);
    assign_kernel<<<NPTS / 64, 256, assign_bytes>>>(x);
    update3_kernel<<<32, 256>>>();
    out_kernel<<<NPTS / 256, 256, out_bytes>>>(x, out);
}

// round 13
// speedup vs baseline: 1.5869x; 1.5869x over previous
#include <cuda_runtime.h>
#include <cuda_bf16.h>
#include <cstdint>
#include <math.h>

#define HDIM 64
#define KDIM 256
#define HW   65536
#define NPTS 262144
#define RATE_F 0.999f
#define EPS_F  1e-6f
#define PADF 257           // fp32 x-tile row pad (floats) -> conflict-free

typedef unsigned long long u64;
typedef unsigned int u32;

// Persistent device scratch (allocation-free rule).
__device__ __align__(16) float g_m  [KDIM * HDIM];   // codebook [k][c]
__device__ __align__(16) float g_mn [KDIM * HDIM];   // normalized [k][c] (out)
__device__ __align__(16) __nv_bfloat16 g_mnh[KDIM * HDIM]; // normalized bf16 [k][c] (assign)
__device__ __align__(16) float g_sum[KDIM * HDIM];
__device__ float g_cnt[KDIM];
__device__ float g_nrm[KDIM];

// ---- packed f32x2 helpers ----
__device__ __forceinline__ u64 pack2(float lo, float hi) {
    u64 r; asm("mov.b64 %0, {%1, %2};" : "=l"(r) : "f"(lo), "f"(hi)); return r;
}
__device__ __forceinline__ void unpack2(u64 v, float& lo, float& hi) {
    asm("mov.b64 {%0, %1}, %2;" : "=f"(lo), "=f"(hi) : "l"(v));
}
__device__ __forceinline__ void fma2(u64& d, u64 a, u64 b) {
    asm("fma.rn.f32x2 %0, %1, %2, %0;" : "+l"(d) : "l"(a), "l"(b));
}
__device__ __forceinline__ u64 add2(u64 a, u64 b) {
    u64 r; asm("add.rn.f32x2 %0, %1, %2;" : "=l"(r) : "l"(a), "l"(b)); return r;
}
__device__ __forceinline__ float ex2f(float x) {
    float r; asm("ex2.approx.f32 %0, %1;" : "=f"(r) : "f"(x)); return r;
}
__device__ __forceinline__ u32 bf2(float hi, float lo) {      // {hi|lo} bf16x2
    u32 r; asm("cvt.rn.bf16x2.f32 %0, %1, %2;" : "=r"(r) : "f"(hi), "f"(lo)); return r;
}
__device__ __forceinline__ uint32_t smem_u32(const void* p) {
    uint32_t a;
    asm("{ .reg .u64 t; cvta.to.shared.u64 t, %1; cvt.u32.u64 %0, t; }" : "=r"(a) : "l"(p));
    return a;
}

// ---------------------------------------------------------------------------
// prep: m = units; mn = normalize(m); bf16 copy; nrm; zero sums.
// ---------------------------------------------------------------------------
__global__ void prep_kernel(const float* __restrict__ units) {
    int warp = threadIdx.x >> 5, lane = threadIdx.x & 31;
    int k = blockIdx.x * 8 + warp;
    if (k >= KDIM) return;
    float v0 = units[k * HDIM + lane];
    float v1 = units[k * HDIM + 32 + lane];
    g_m[k * HDIM + lane]      = v0;
    g_m[k * HDIM + 32 + lane] = v1;
    float ssq = v0 * v0 + v1 * v1;
    #pragma unroll
    for (int o = 16; o; o >>= 1) ssq += __shfl_xor_sync(0xFFFFFFFFu, ssq, o);
    float nrm = sqrtf(ssq);
    float inv = 1.0f / fmaxf(nrm, 1e-12f);
    float n0 = v0 * inv, n1 = v1 * inv;
    g_mn[k * HDIM + lane]      = n0;
    g_mn[k * HDIM + 32 + lane] = n1;
    g_mnh[k * HDIM + lane]      = __float2bfloat16(n0);
    g_mnh[k * HDIM + 32 + lane] = __float2bfloat16(n1);
    g_sum[k * HDIM + lane]      = 0.0f;
    g_sum[k * HDIM + 32 + lane] = 0.0f;
    if (lane == 0) { g_cnt[k] = 0.0f; g_nrm[k] = nrm; }
}

// ---------------------------------------------------------------------------
// assign via mma.sync bf16 (HMMA): CTA = 256 pts, 8 warps; warp = 32 pts x
// 256 k (K=64). A(x) frags in regs (one-time, from fp32 smem via cvt),
// B(mn) via ldmatrix.x2.trans from 144B-stride bf16 tile (conflict-free
// LDSM). Running per-point argmax across n-chunks, quad-reduce, scatter.
// smem ~101 KB, 2 CTAs/SM.
// ---------------------------------------------------------------------------
#define S_XF   0                       // 64 * 257 * 4 = 65792
#define S_MN   65792                   // 256 * 144   = 36864
#define S_BK   102656                  // 256 * 4     = 1024
#define S_TOT  103680

__global__ void __launch_bounds__(256, 2) assign_kernel(const float* __restrict__ x) {
    extern __shared__ __align__(16) unsigned char smem[];
    float* sxf = (float*)(smem + S_XF);            // [64 c][257 pts]
    unsigned char* smn = smem + S_MN;              // [256 k][144 B] bf16 rows
    int*   sbk = (int*)(smem + S_BK);
    int tid = threadIdx.x;

    // Load x (coalesced) into fp32 [c][257].
    int hw0 = blockIdx.x * 256;
    int b   = hw0 >> 16;
    const float* xg = x + (size_t)b * HDIM * HW + (hw0 & (HW - 1));
    #pragma unroll 4
    for (int i = tid; i < HDIM * 256; i += 256) {
        int c = i >> 8, pt = i & 255;
        sxf[c * PADF + pt] = xg[(size_t)c * HW + pt];
    }
    // Copy mn bf16 [k][128B] -> smem [k][144B stride] in 16B chunks.
    {
        const uint4* src = (const uint4*)g_mnh;
        #pragma unroll 4
        for (int i = tid; i < KDIM * 8; i += 256) {
            int k = i >> 3, ch = i & 7;
            *(uint4*)(smn + k * 144 + ch * 16) = src[k * 8 + ch];
        }
    }
    __syncthreads();

    int w = tid >> 5, lane = tid & 31;
    int g = lane >> 2, q = lane & 3;
    int wBase = w * 32;

    // Build A fragments: A[t][jc][4], t = m-tile (16 pts), jc = k-chunk (16 c).
    u32 A[2][4][4];
    #pragma unroll
    for (int t = 0; t < 2; t++) {
        int p0 = wBase + 16 * t + g;
        int p1 = p0 + 8;
        #pragma unroll
        for (int jc = 0; jc < 4; jc++) {
            int c0 = 16 * jc + 2 * q;
            float a00 = sxf[(c0)     * PADF + p0], a01 = sxf[(c0 + 1) * PADF + p0];
            float a10 = sxf[(c0)     * PADF + p1], a11 = sxf[(c0 + 1) * PADF + p1];
            float a02 = sxf[(c0 + 8) * PADF + p0], a03 = sxf[(c0 + 9) * PADF + p0];
            float a12 = sxf[(c0 + 8) * PADF + p1], a13 = sxf[(c0 + 9) * PADF + p1];
            A[t][jc][0] = bf2(a01, a00);
            A[t][jc][1] = bf2(a11, a10);
            A[t][jc][2] = bf2(a03, a02);
            A[t][jc][3] = bf2(a13, a12);
        }
    }

    // ldmatrix row address (per-thread, lanes 0..15 used for .x2).
    u32 mnS = smem_u32(smn);
    u32 rowAddr = mnS + (u32)((lane & 7) * 144) + ((lane & 8) ? 16u : 0u);

    float best[4] = {-1e30f, -1e30f, -1e30f, -1e30f};
    int   bkk[4]  = {0, 0, 0, 0};

    for (int n0 = 0; n0 < KDIM; n0 += 8) {
        float d0[4] = {0.f, 0.f, 0.f, 0.f};
        float d1[4] = {0.f, 0.f, 0.f, 0.f};
        #pragma unroll
        for (int jc = 0; jc < 4; jc++) {
            u32 b0, b1;
            asm volatile("ldmatrix.sync.aligned.m8n8.x2.trans.shared.b16 {%0,%1}, [%2];"
                         : "=r"(b0), "=r"(b1)
                         : "r"(rowAddr + (u32)(n0 * 144 + jc * 32)));
            asm volatile("mma.sync.aligned.m16n8k16.row.col.f32.bf16.bf16.f32 "
                         "{%0,%1,%2,%3}, {%4,%5,%6,%7}, {%8,%9}, {%0,%1,%2,%3};"
                         : "+f"(d0[0]), "+f"(d0[1]), "+f"(d0[2]), "+f"(d0[3])
                         : "r"(A[0][jc][0]), "r"(A[0][jc][1]), "r"(A[0][jc][2]), "r"(A[0][jc][3]),
                           "r"(b0), "r"(b1));
            asm volatile("mma.sync.aligned.m16n8k16.row.col.f32.bf16.bf16.f32 "
                         "{%0,%1,%2,%3}, {%4,%5,%6,%7}, {%8,%9}, {%0,%1,%2,%3};"
                         : "+f"(d1[0]), "+f"(d1[1]), "+f"(d1[2]), "+f"(d1[3])
                         : "r"(A[1][jc][0]), "r"(A[1][jc][1]), "r"(A[1][jc][2]), "r"(A[1][jc][3]),
                           "r"(b0), "r"(b1));
        }
        int k0 = n0 + 2 * q, k1 = k0 + 1;
        if (d0[0] > best[0]) { best[0] = d0[0]; bkk[0] = k0; }
        if (d0[1] > best[0]) { best[0] = d0[1]; bkk[0] = k1; }
        if (d0[2] > best[1]) { best[1] = d0[2]; bkk[1] = k0; }
        if (d0[3] > best[1]) { best[1] = d0[3]; bkk[1] = k1; }
        if (d1[0] > best[2]) { best[2] = d1[0]; bkk[2] = k0; }
        if (d1[1] > best[2]) { best[2] = d1[1]; bkk[2] = k1; }
        if (d1[2] > best[3]) { best[3] = d1[2]; bkk[3] = k0; }
        if (d1[3] > best[3]) { best[3] = d1[3]; bkk[3] = k1; }
    }

    // Quad reduce (lanes sharing a row: xor 1, xor 2), min-k tie-break.
    #pragma unroll
    for (int r = 0; r < 4; r++) {
        #pragma unroll
        for (int o = 1; o <= 2; o <<= 1) {
            float ov = __shfl_xor_sync(0xFFFFFFFFu, best[r], o);
            int   ok = __shfl_xor_sync(0xFFFFFFFFu, bkk[r],  o);
            if (ov > best[r] || (ov == best[r] && ok < bkk[r])) { best[r] = ov; bkk[r] = ok; }
        }
    }
    if (q == 0) {
        sbk[wBase + g]      = bkk[0];
        sbk[wBase + g + 8]  = bkk[1];
        sbk[wBase + 16 + g] = bkk[2];
        sbk[wBase + 24 + g] = bkk[3];
    }
    __syncwarp();

    // Warp-cooperative fp32 scatter of this warp's 32 points.
    #pragma unroll 4
    for (int pl = 0; pl < 32; pl++) {
        int pt = wBase + pl;
        int bk = sbk[pt];
        float v0 = sxf[lane * PADF + pt];
        float v1 = sxf[(32 + lane) * PADF + pt];
        atomicAdd(g_sum + bk * HDIM + lane,      v0);
        atomicAdd(g_sum + bk * HDIM + 32 + lane, v1);
        if (lane == 0) atomicAdd(g_cnt + bk, 1.0f);
    }
}

// ---------------------------------------------------------------------------
// update3: closed-form 3-step EMA with frozen assignments.
// ---------------------------------------------------------------------------
__global__ void update3_kernel() {
    int warp = threadIdx.x >> 5, lane = threadIdx.x & 31;
    int k = blockIdx.x * 8 + warp;
    if (k >= KDIM) return;
    const float R3  = RATE_F * RATE_F * RATE_F;
    const float IR3 = 1.0f - R3;
    float sc = IR3 / (g_cnt[k] + EPS_F);
    float m0 = g_m[k * HDIM + lane]      * R3 + g_sum[k * HDIM + lane]      * sc;
    float m1 = g_m[k * HDIM + 32 + lane] * R3 + g_sum[k * HDIM + 32 + lane] * sc;
    g_m[k * HDIM + lane]      = m0;
    g_m[k * HDIM + 32 + lane] = m1;
    float ssq = m0 * m0 + m1 * m1;
    #pragma unroll
    for (int o = 16; o; o >>= 1) ssq += __shfl_xor_sync(0xFFFFFFFFu, ssq, o);
    float nrm = sqrtf(ssq);
    float inv = 1.0f / fmaxf(nrm, 1e-12f);
    g_mn[k * HDIM + lane]      = m0 * inv;
    g_mn[k * HDIM + 32 + lane] = m1 * inv;
    if (lane == 0) g_nrm[k] = nrm;
}

// ---------------------------------------------------------------------------
// out (R11 form — best measured): 1 pt/thread, single softmax pass, xr
// pre-scaled by invn*log2e, bare ex2, m_k = mn_k * nrm_k. 128-thr, 2 CTA/SM.
// ---------------------------------------------------------------------------
__global__ void __launch_bounds__(128, 2) out_kernel(const float* __restrict__ x,
                                                     float* __restrict__ out) {
    extern __shared__ ulonglong2 smem_raw[];
    ulonglong2* smq = smem_raw;                                  // mn: 4096 x 16B
    float* snrm = (float*)(smem_raw + KDIM * HDIM / 4);          // nrm: 256 floats
    const ulonglong2* gm = (const ulonglong2*)g_mn;
    #pragma unroll 8
    for (int i = threadIdx.x; i < KDIM * HDIM / 4; i += 128) smq[i] = gm[i];
    #pragma unroll 2
    for (int i = threadIdx.x; i < KDIM; i += 128) snrm[i] = g_nrm[i];
    __syncthreads();

    int p  = blockIdx.x * 128 + threadIdx.x;
    int b  = p >> 16;
    const float* xb = x + (size_t)b * HDIM * HW + (p & (HW - 1));

    float xf[HDIM];
    float s0 = 0.f, s1 = 0.f;
    #pragma unroll
    for (int i = 0; i < HDIM; i += 2) {
        float f0 = xb[(size_t)i * HW];
        float f1 = xb[(size_t)(i + 1) * HW];
        xf[i] = f0; xf[i + 1] = f1;
        s0 = fmaf(f0, f0, s0);
        s1 = fmaf(f1, f1, s1);
    }
    float scl = 1.44269504088896f / fmaxf(sqrtf(s0 + s1), 1e-12f);
    u64 xr[HDIM / 2];
    #pragma unroll
    for (int i = 0; i < HDIM / 2; i++)
        xr[i] = pack2(xf[2 * i] * scl, xf[2 * i + 1] * scl);

    u64 acc[HDIM / 2];
    #pragma unroll
    for (int i = 0; i < HDIM / 2; i++) acc[i] = 0ull;
    float den = 0.0f;

    for (int k = 0; k < KDIM; k++) {
        u64 v[HDIM / 2];
        const ulonglong2* row = smq + k * 16;
        #pragma unroll
        for (int i = 0; i < 16; i++) { ulonglong2 q = row[i]; v[2 * i] = q.x; v[2 * i + 1] = q.y; }
        u64 d0 = 0ull, d1 = 0ull;
        #pragma unroll
        for (int i = 0; i < 16; i++) {
            fma2(d0, xr[2 * i],     v[2 * i]);
            fma2(d1, xr[2 * i + 1], v[2 * i + 1]);
        }
        float e0, e1;
        unpack2(add2(d0, d1), e0, e1);
        float e = ex2f(e0 + e1);
        den += e;
        float wv = e * snrm[k];
        u64 w2 = pack2(wv, wv);
        #pragma unroll
        for (int i = 0; i < HDIM / 2; i++) fma2(acc[i], w2, v[i]);
    }

    float iden = 1.0f / den;
    float* ob = out + (size_t)b * HDIM * HW + (p & (HW - 1));
    #pragma unroll
    for (int i = 0; i < HDIM / 2; i++) {
        float f0, f1;
        unpack2(acc[i], f0, f1);
        ob[(size_t)(2 * i) * HW]     = f0 * iden;
        ob[(size_t)(2 * i + 1) * HW] = f1 * iden;
    }
}

// ---------------------------------------------------------------------------
extern "C" void kernel_launch(void* const* d_in, const int* in_sizes, int n_in,
                              void* d_out, int out_size) {
    const float* x;
    const float* units;
    if (in_sizes[0] >= in_sizes[1]) { x = (const float*)d_in[0]; units = (const float*)d_in[1]; }
    else                            { x = (const float*)d_in[1]; units = (const float*)d_in[0]; }
    float* out = (float*)d_out;

    const int out_bytes = (KDIM * HDIM + KDIM) * (int)sizeof(float);   // 65 KB
    cudaFuncSetAttribute(assign_kernel, cudaFuncAttributeMaxDynamicSharedMemorySize, S_TOT);
    cudaFuncSetAttribute(out_kernel,    cudaFuncAttributeMaxDynamicSharedMemorySize, out_bytes);

    prep_kernel<<<32, 256>>>(units);
    assign_kernel<<<NPTS / 256, 256, S_TOT>>>(x);
    update3_kernel<<<32, 256>>>();
    out_kernel<<<NPTS / 128, 128, out_bytes>>>(x, out);
}